// round 13
// baseline (speedup 1.0000x reference)
#include <cuda_runtime.h>
#include <cstdint>

// PointPillars scatter, inverted as index-map + gather (PDL-chained).
// B=4, C=64, H=512, W=512, P read from in_sizes.
//
// Init-free map: g_map holds (pid+1), 0 = empty. Zero-initialized at module
// load; gather self-cleans consumed cells so every graph replay starts from
// a clean map (gather -> next-replay scatter is stream-ordered).
//
// Evidence matrix (rounds 5-12): gather pinned at 58-60us, DRAM~65%,
// invariant to occupancy/cache/store-width; block barriers after random
// reads are catastrophic (r7); grid-barrier fusion loses to PDL (r11).
// This round attacks the last unsaturated-but-loaded resource: L1tex
// wavefront replays on the scattered feature loads. Loads are made
// warp-cooperative (two contiguous 256B rows per round) staged through a
// WARP-PRIVATE smem tile — __syncwarp only, zero cross-warp coupling.
#define B_ 4
#define C_ 64
#define H_ 512
#define W_ 512
#define HW_ (H_ * W_)        // 262144 = 2^18
#define BHW_ (B_ * HW_)      // 1048576

#define ROWSTRIDE_ 68        // floats; 272B = 17*16B -> 16B-aligned, conflict-free

__device__ int g_map[BHW_];  // zero-initialized at load; 0 = empty

// ---------------------------------------------------------------------------
// Kernel 1: scatter (pid+1) per pillar. atomicMax => highest pillar index
// wins == the reference's sequential last-write-wins.
__global__ void __launch_bounds__(512) k_scatter_idx(const int* __restrict__ coords, int P) {
    int p = blockIdx.x * blockDim.x + threadIdx.x;
    if (p < P) {
        int4 c = __ldcs(reinterpret_cast<const int4*>(coords) + p);  // [b,z,y,x]
        int b = c.x, y = c.z, x = c.w;
        if ((unsigned)y < H_ && (unsigned)x < W_) {
            atomicMax(&g_map[(b * H_ + y) * W_ + x], p + 1);
        }
    }
    cudaTriggerProgrammaticLaunchCompletion();
}

// ---------------------------------------------------------------------------
// Kernel 2: gather + self-clean, warp-private smem transpose.
// Block = 128 threads = 4 warps; each warp owns 32 consecutive cells and a
// private 32x68-float tile. Load phase: 16 rounds, half-warp per row, each
// occupied feature row read as contiguous 256B (2 lines). Store phase =
// round-9 epilogue: lane owns its cell, 64 strided channel stores coalesced
// across the warp in w (streaming). No __syncthreads anywhere.
__global__ void __launch_bounds__(128) k_gather(const float* __restrict__ feat,
                                                float* __restrict__ out) {
    __shared__ float s_f[4][32][ROWSTRIDE_];

    const int warp = threadIdx.x >> 5;
    const int lane = threadIdx.x & 31;
    const int s = blockIdx.x * 128 + threadIdx.x;   // this lane's cell
    const int b  = s >> 18;
    const int sp = s & (HW_ - 1);

    cudaGridDependencySynchronize();   // scatter grid fully complete

    int v = g_map[s];
    if (v > 0) g_map[s] = 0;           // self-clean for next graph replay

    // ---- load phase: warp-cooperative, 2 rows per round ----
    const int half = lane >> 4;        // 0/1: which of the round's two cells
    const int t    = lane & 15;        // float4 index within the 256B row
#pragma unroll
    for (int r2 = 0; r2 < 16; r2++) {
        int cell = 2 * r2 + half;
        int pv = __shfl_sync(0xffffffffu, v, cell);
        if (pv > 0) {
            float4 a = __ldcs(reinterpret_cast<const float4*>(feat)
                              + (size_t)(pv - 1) * 16 + t);
            *reinterpret_cast<float4*>(&s_f[warp][cell][4 * t]) = a;
        }
    }
    __syncwarp();

    // ---- store phase: lane = own cell (round-9 proven epilogue) ----
    float4 r[16];
    if (v > 0) {
#pragma unroll
        for (int i = 0; i < 16; i++)
            r[i] = *reinterpret_cast<float4*>(&s_f[warp][lane][4 * i]);
    } else {
#pragma unroll
        for (int i = 0; i < 16; i++) r[i] = make_float4(0.f, 0.f, 0.f, 0.f);
    }

    float* op = out + (size_t)b * (C_ * HW_) + sp;
#pragma unroll
    for (int i = 0; i < 16; i++) {
        __stcs(op + (size_t)(4 * i + 0) * HW_, r[i].x);
        __stcs(op + (size_t)(4 * i + 1) * HW_, r[i].y);
        __stcs(op + (size_t)(4 * i + 2) * HW_, r[i].z);
        __stcs(op + (size_t)(4 * i + 3) * HW_, r[i].w);
    }
}

// ---------------------------------------------------------------------------
extern "C" void kernel_launch(void* const* d_in, const int* in_sizes, int n_in,
                              void* d_out, int out_size) {
    const float* feat   = (const float*)d_in[0];   // [P, C] float32
    const int*   coords = (const int*)d_in[1];     // [P, 4] int32
    int P = in_sizes[1] / 4;

    k_scatter_idx<<<(P + 511) / 512, 512>>>(coords, P);

    // Gather with programmatic dependent launch on the scatter.
    cudaLaunchConfig_t cfg = {};
    cfg.gridDim  = dim3(BHW_ / 128);
    cfg.blockDim = dim3(128);
    cfg.stream   = 0;  // capture stream
    cudaLaunchAttribute attr[1];
    attr[0].id = cudaLaunchAttributeProgrammaticStreamSerialization;
    attr[0].val.programmaticStreamSerializationAllowed = 1;
    cfg.attrs    = attr;
    cfg.numAttrs = 1;
    cudaLaunchKernelEx(&cfg, k_gather, feat, (float*)d_out);
}